// round 15
// baseline (speedup 1.0000x reference)
#include <cuda_runtime.h>
#include <cstddef>
#include <cstdint>

#define LSEQ 2048
#define DM   1024
#define DIN  2048
#define NST  16
#define DTR  64
#define XD   96     // DTR + 2*NST
#define KCONV 4
#define NCHK 8      // suffix-scan chunks
#define CHK  256    // timesteps per chunk

// ---------------- scratch (device globals; no allocation allowed) ----------------
__device__ float g_xr[(size_t)LSEQ * 2 * DIN];            // [xi_raw | res]
__device__ float g_xi[(size_t)LSEQ * DIN];                // conv+swish output (u)
__device__ float g_xdbl[(size_t)LSEQ * XD];               // delta_r | B | C
__device__ float g_xdbl_hi[(size_t)LSEQ * XD];
__device__ float g_xdbl_lo[(size_t)LSEQ * XD];
__device__ float g_delta[(size_t)LSEQ * DIN];
__device__ float g_R[(size_t)LSEQ * DIN];                 // suffix sums, [t][d] layout
__device__ float g_S[(size_t)NCHK * DIN];                 // per-chunk channel sums
__device__ float g_yacc[(size_t)LSEQ * DIN];              // scan C-projection accumulator
__device__ float g_y[(size_t)LSEQ * DIN];                 // gated scan output (tf32-rounded)
__device__ float g_part[(size_t)8 * LSEQ * XD];           // split-K partials for GEMM2
__device__ float g_xhi[(size_t)LSEQ * DM];                // tf32 hi of x
__device__ float g_xlo[(size_t)LSEQ * DM];                // tf32 lo of x
__device__ float g_w1hi[(size_t)DM * DIN];                // hi of W_in[:, :DIN]
__device__ float g_w1lo[(size_t)DM * DIN];                // lo of W_in[:, :DIN]
__device__ float g_wres[(size_t)DM * DIN];                // hi of W_in[:, DIN:]
__device__ float g_wout[(size_t)DIN * DM];                // hi of W_out
__device__ float g_wdthi[(size_t)DTR * DIN];              // hi of W_dt
__device__ float g_wdtlo[(size_t)DTR * DIN];              // lo of W_dt

// ---------------- helpers ----------------
__device__ __forceinline__ float fast_exp(float x) {
    float y;
    asm("ex2.approx.f32 %0, %1;" : "=f"(y) : "f"(x * 1.4426950408889634f));
    return y;
}
__device__ __forceinline__ float fast_rcp(float x) {
    float y;
    asm("rcp.approx.f32 %0, %1;" : "=f"(y) : "f"(x));
    return y;
}
__device__ __forceinline__ float swish_f(float v) {
    return v / (1.0f + fast_exp(-v));
}
__device__ __forceinline__ float softplus_f(float v) {
    return log1pf(fast_exp(-fabsf(v))) + fmaxf(v, 0.0f);
}
__device__ __forceinline__ float tf32_rna(float x) {
    uint32_t u;
    asm("cvt.rna.tf32.f32 %0, %1;" : "=r"(u) : "f"(x));
    return __uint_as_float(u);
}
__device__ __forceinline__ float4 tf32_rna4(float4 v) {
    return make_float4(tf32_rna(v.x), tf32_rna(v.y), tf32_rna(v.z), tf32_rna(v.w));
}
__device__ __forceinline__ void mma8(float* d, const uint32_t* a, const uint32_t* b) {
    asm volatile("mma.sync.aligned.m16n8k8.row.col.f32.tf32.tf32.f32 "
        "{%0,%1,%2,%3}, {%4,%5,%6,%7}, {%8,%9}, {%0,%1,%2,%3};"
        : "+f"(d[0]), "+f"(d[1]), "+f"(d[2]), "+f"(d[3])
        : "r"(a[0]), "r"(a[1]), "r"(a[2]), "r"(a[3]), "r"(b[0]), "r"(b[1]));
}
__device__ __forceinline__ void cp_async16(void* smem_dst, const void* gsrc) {
    uint32_t d = (uint32_t)__cvta_generic_to_shared(smem_dst);
    asm volatile("cp.async.ca.shared.global [%0], [%1], 16;" :: "r"(d), "l"(gsrc));
}

constexpr int AST = 36;
constexpr int BST = 136;
constexpr int ASZ = 128 * AST;
constexpr int BSZ = 32 * BST;

// =============== FUSED GEMM1: xi_raw (3xTF32) + res (plain TF32), one launch ===
__global__ void __launch_bounds__(256)
gemm1_fused_kernel(const float* __restrict__ xhi, const float* __restrict__ xlo,
                   const float* __restrict__ w1hi, const float* __restrict__ w1lo,
                   const float* __restrict__ wres, float* __restrict__ xr)
{
    extern __shared__ float sm[];
    const int tid  = threadIdx.x;
    const int wid  = tid >> 5;
    const int lane = tid & 31;
    const int g    = lane >> 2;
    const int tg   = lane & 3;
    const int wm0  = (wid >> 2) << 6;
    const int wn0  = (wid & 3) << 5;
    const int m0   = blockIdx.y << 7;
    const bool three = (blockIdx.x < 16);
    const int n0   = (three ? blockIdx.x : (blockIdx.x - 16)) << 7;
    const int cbase = three ? 0 : DIN;

    float acc[4][4][4];
#pragma unroll
    for (int i = 0; i < 4; i++)
#pragma unroll
        for (int j = 0; j < 4; j++)
#pragma unroll
            for (int q = 0; q < 4; q++) acc[i][j][q] = 0.0f;

    const int nt = DM >> 5;   // 32 k-tiles

    if (three) {
        constexpr int STAGE = 2 * (ASZ + BSZ);
        auto issue_stage = [&](int s, int k0) {
            float* As_h = sm + s * STAGE;
            float* As_l = As_h + ASZ;
            float* Bs_h = As_h + 2 * ASZ;
            float* Bs_l = Bs_h + BSZ;
#pragma unroll
            for (int i = 0; i < 4; i++) {
                int lin = tid + (i << 8);
                int arow = lin >> 3, acol = (lin & 7) << 2;
                size_t aoff = (size_t)(m0 + arow) * DM + k0 + acol;
                cp_async16(As_h + arow * AST + acol, xhi + aoff);
                cp_async16(As_l + arow * AST + acol, xlo + aoff);
                int brow = lin >> 5, bcol = (lin & 31) << 2;
                size_t boff = (size_t)(k0 + brow) * DIN + n0 + bcol;
                cp_async16(Bs_h + brow * BST + bcol, w1hi + boff);
                cp_async16(Bs_l + brow * BST + bcol, w1lo + boff);
            }
            asm volatile("cp.async.commit_group;");
        };
        auto compute = [&](int s) {
            const float* As_h = sm + s * STAGE;
            const float* As_l = As_h + ASZ;
            const float* Bs_h = As_h + 2 * ASZ;
            const float* Bs_l = Bs_h + BSZ;
#pragma unroll
            for (int j = 0; j < 4; j++) {
                const int kk = j << 3;
                uint32_t ah[4][4], al[4][4], bh[4][2], bl[4][2];
#pragma unroll
                for (int nf = 0; nf < 4; nf++) {
                    int bn = wn0 + (nf << 3) + g;
                    bh[nf][0] = __float_as_uint(Bs_h[(kk + tg) * BST + bn]);
                    bh[nf][1] = __float_as_uint(Bs_h[(kk + tg + 4) * BST + bn]);
                    bl[nf][0] = __float_as_uint(Bs_l[(kk + tg) * BST + bn]);
                    bl[nf][1] = __float_as_uint(Bs_l[(kk + tg + 4) * BST + bn]);
                }
#pragma unroll
                for (int mf = 0; mf < 4; mf++) {
                    int rm = (wm0 + (mf << 4) + g) * AST + kk + tg;
                    ah[mf][0] = __float_as_uint(As_h[rm]);
                    ah[mf][1] = __float_as_uint(As_h[rm + 8 * AST]);
                    ah[mf][2] = __float_as_uint(As_h[rm + 4]);
                    ah[mf][3] = __float_as_uint(As_h[rm + 8 * AST + 4]);
                    al[mf][0] = __float_as_uint(As_l[rm]);
                    al[mf][1] = __float_as_uint(As_l[rm + 8 * AST]);
                    al[mf][2] = __float_as_uint(As_l[rm + 4]);
                    al[mf][3] = __float_as_uint(As_l[rm + 8 * AST + 4]);
                }
#pragma unroll
                for (int mf = 0; mf < 4; mf++)
#pragma unroll
                    for (int nf = 0; nf < 4; nf++) {
                        mma8(acc[mf][nf], ah[mf], bh[nf]);
                        mma8(acc[mf][nf], ah[mf], bl[nf]);
                        mma8(acc[mf][nf], al[mf], bh[nf]);
                    }
            }
        };
        issue_stage(0, 0);
        asm volatile("cp.async.wait_group 0;");
        __syncthreads();
        for (int t = 0; t < nt; t++) {
            if (t + 1 < nt) issue_stage((t + 1) & 1, (t + 1) << 5);
            compute(t & 1);
            if (t + 1 < nt) {
                asm volatile("cp.async.wait_group 0;");
                __syncthreads();
            }
        }
    } else {
        constexpr int STAGE = ASZ + BSZ;
        auto issue_stage = [&](int s, int k0) {
            float* As = sm + s * STAGE;
            float* Bs = As + ASZ;
#pragma unroll
            for (int i = 0; i < 4; i++) {
                int lin = tid + (i << 8);
                int arow = lin >> 3, acol = (lin & 7) << 2;
                cp_async16(As + arow * AST + acol, xhi + (size_t)(m0 + arow) * DM + k0 + acol);
                int brow = lin >> 5, bcol = (lin & 31) << 2;
                cp_async16(Bs + brow * BST + bcol, wres + (size_t)(k0 + brow) * DIN + n0 + bcol);
            }
            asm volatile("cp.async.commit_group;");
        };
        auto compute = [&](int s) {
            const float* As = sm + s * STAGE;
            const float* Bs = As + ASZ;
#pragma unroll
            for (int j = 0; j < 4; j++) {
                const int kk = j << 3;
                uint32_t ah[4][4], bh[4][2];
#pragma unroll
                for (int nf = 0; nf < 4; nf++) {
                    int bn = wn0 + (nf << 3) + g;
                    bh[nf][0] = __float_as_uint(Bs[(kk + tg) * BST + bn]);
                    bh[nf][1] = __float_as_uint(Bs[(kk + tg + 4) * BST + bn]);
                }
#pragma unroll
                for (int mf = 0; mf < 4; mf++) {
                    int rm = (wm0 + (mf << 4) + g) * AST + kk + tg;
                    ah[mf][0] = __float_as_uint(As[rm]);
                    ah[mf][1] = __float_as_uint(As[rm + 8 * AST]);
                    ah[mf][2] = __float_as_uint(As[rm + 4]);
                    ah[mf][3] = __float_as_uint(As[rm + 8 * AST + 4]);
                }
#pragma unroll
                for (int mf = 0; mf < 4; mf++)
#pragma unroll
                    for (int nf = 0; nf < 4; nf++)
                        mma8(acc[mf][nf], ah[mf], bh[nf]);
            }
        };
        issue_stage(0, 0);
        issue_stage(1, 32);
        asm volatile("cp.async.wait_group 1;");
        __syncthreads();
        for (int t = 0; t < nt; t++) {
            compute(t % 3);
            if (t + 1 < nt) {
                if (t + 2 < nt) {
                    issue_stage((t + 2) % 3, (t + 2) << 5);
                    asm volatile("cp.async.wait_group 1;");
                } else {
                    asm volatile("cp.async.wait_group 0;");
                }
                __syncthreads();
            }
        }
    }

#pragma unroll
    for (int mf = 0; mf < 4; mf++)
#pragma unroll
        for (int nf = 0; nf < 4; nf++) {
            int row = m0 + wm0 + (mf << 4) + g;
            int col = cbase + n0 + wn0 + (nf << 3) + (tg << 1);
            *(float2*)(xr + (size_t)row * (2 * DIN) + col) =
                make_float2(acc[mf][nf][0], acc[mf][nf][1]);
            *(float2*)(xr + (size_t)(row + 8) * (2 * DIN) + col) =
                make_float2(acc[mf][nf][2], acc[mf][nf][3]);
        }
}

// =============== 3xTF32 tensor GEMM (register-staged; measured-good GEMM2) =====
template<bool THREE, int MODE>
__global__ void __launch_bounds__(256)
gemm_tf32_kernel(const float* __restrict__ A, const float* __restrict__ B,
                 const float* __restrict__ bias, float* __restrict__ C,
                 int M, int N, int K, int lda, int ldb, int ldc)
{
    extern __shared__ float sm[];
    constexpr int STAGE = THREE ? 2 * (ASZ + BSZ) : (ASZ + BSZ);

    const int tid  = threadIdx.x;
    const int wid  = tid >> 5;
    const int lane = tid & 31;
    const int g    = lane >> 2;
    const int tg   = lane & 3;
    const int wm0  = (wid >> 2) << 6;
    const int wn0  = (wid & 3) << 5;
    const int m0   = blockIdx.y << 7;
    const int n0   = blockIdx.x << 7;

    const int splits = gridDim.z;
    const int Kc = K / splits;
    const int kbeg = blockIdx.z * Kc;

    float acc[4][4][4];
#pragma unroll
    for (int i = 0; i < 4; i++)
#pragma unroll
        for (int j = 0; j < 4; j++)
#pragma unroll
            for (int q = 0; q < 4; q++) acc[i][j][q] = 0.0f;

    float4 ra[4], rb[4];

    auto ldg_tile = [&](int k0) {
#pragma unroll
        for (int i = 0; i < 4; i++) {
            int lin = tid + (i << 8);
            ra[i] = *(const float4*)(A + (size_t)(m0 + (lin >> 3)) * lda + k0 + ((lin & 7) << 2));
            int gn = n0 + ((lin & 31) << 2);
            if (gn + 3 < N)
                rb[i] = *(const float4*)(B + (size_t)(k0 + (lin >> 5)) * ldb + gn);
            else
                rb[i] = make_float4(0.f, 0.f, 0.f, 0.f);
        }
    };

    auto sts_tile = [&](int s) {
        float* As_h = sm + s * STAGE;
        float* Bs_h = As_h + (THREE ? 2 * ASZ : ASZ);
#pragma unroll
        for (int i = 0; i < 4; i++) {
            int lin = tid + (i << 8);
            int arow = lin >> 3, acol = (lin & 7) << 2;
            float4 h = tf32_rna4(ra[i]);
            *(float4*)(As_h + arow * AST + acol) = h;
            if (THREE) {
                float4 l;
                l.x = tf32_rna(ra[i].x - h.x); l.y = tf32_rna(ra[i].y - h.y);
                l.z = tf32_rna(ra[i].z - h.z); l.w = tf32_rna(ra[i].w - h.w);
                *(float4*)(As_h + ASZ + arow * AST + acol) = l;
            }
            int brow = lin >> 5, bcol = (lin & 31) << 2;
            float4 bh = tf32_rna4(rb[i]);
            *(float4*)(Bs_h + brow * BST + bcol) = bh;
            if (THREE) {
                float4 bl;
                bl.x = tf32_rna(rb[i].x - bh.x); bl.y = tf32_rna(rb[i].y - bh.y);
                bl.z = tf32_rna(rb[i].z - bh.z); bl.w = tf32_rna(rb[i].w - bh.w);
                *(float4*)(Bs_h + BSZ + brow * BST + bcol) = bl;
            }
        }
    };

    auto compute = [&](int s) {
        const float* As_h = sm + s * STAGE;
        const float* As_l = As_h + ASZ;
        const float* Bs_h = As_h + (THREE ? 2 * ASZ : ASZ);
        const float* Bs_l = Bs_h + BSZ;
#pragma unroll
        for (int j = 0; j < 4; j++) {
            const int kk = j << 3;
            uint32_t ah[4][4], bh[4][2];
            uint32_t al[4][4], bl[4][2];
#pragma unroll
            for (int nf = 0; nf < 4; nf++) {
                int bn = wn0 + (nf << 3) + g;
                bh[nf][0] = __float_as_uint(Bs_h[(kk + tg) * BST + bn]);
                bh[nf][1] = __float_as_uint(Bs_h[(kk + tg + 4) * BST + bn]);
                if (THREE) {
                    bl[nf][0] = __float_as_uint(Bs_l[(kk + tg) * BST + bn]);
                    bl[nf][1] = __float_as_uint(Bs_l[(kk + tg + 4) * BST + bn]);
                }
            }
#pragma unroll
            for (int mf = 0; mf < 4; mf++) {
                int rm = (wm0 + (mf << 4) + g) * AST + kk + tg;
                ah[mf][0] = __float_as_uint(As_h[rm]);
                ah[mf][1] = __float_as_uint(As_h[rm + 8 * AST]);
                ah[mf][2] = __float_as_uint(As_h[rm + 4]);
                ah[mf][3] = __float_as_uint(As_h[rm + 8 * AST + 4]);
                if (THREE) {
                    al[mf][0] = __float_as_uint(As_l[rm]);
                    al[mf][1] = __float_as_uint(As_l[rm + 8 * AST]);
                    al[mf][2] = __float_as_uint(As_l[rm + 4]);
                    al[mf][3] = __float_as_uint(As_l[rm + 8 * AST + 4]);
                }
            }
#pragma unroll
            for (int mf = 0; mf < 4; mf++)
#pragma unroll
                for (int nf = 0; nf < 4; nf++) {
                    mma8(acc[mf][nf], ah[mf], bh[nf]);
                    if (THREE) {
                        mma8(acc[mf][nf], ah[mf], bl[nf]);
                        mma8(acc[mf][nf], al[mf], bh[nf]);
                    }
                }
        }
    };

    const int nt = Kc >> 5;
    ldg_tile(kbeg);
    sts_tile(0);
    __syncthreads();
    for (int t = 0; t < nt; t++) {
        if (t + 1 < nt) ldg_tile(kbeg + ((t + 1) << 5));
        compute(t & 1);
        if (t + 1 < nt) {
            __syncthreads();
            sts_tile((t + 1) & 1);
            __syncthreads();
        }
    }

    float* Cout = C + (size_t)blockIdx.z * M * ldc;

#pragma unroll
    for (int mf = 0; mf < 4; mf++)
#pragma unroll
        for (int nf = 0; nf < 4; nf++) {
            int row = m0 + wm0 + (mf << 4) + g;
            int col = n0 + wn0 + (nf << 3) + (tg << 1);
            if (col + 1 >= N) continue;
            float b0 = 0.0f, b1 = 0.0f;
            if (MODE >= 1 && splits == 1) { b0 = bias[col]; b1 = bias[col + 1]; }
            float v00 = acc[mf][nf][0] + b0, v01 = acc[mf][nf][1] + b1;
            float v10 = acc[mf][nf][2] + b0, v11 = acc[mf][nf][3] + b1;
            if (MODE == 2 && splits == 1) {
                v00 = softplus_f(v00); v01 = softplus_f(v01);
                v10 = softplus_f(v10); v11 = softplus_f(v11);
            }
            *(float2*)(Cout + (size_t)row * ldc + col) = make_float2(v00, v01);
            *(float2*)(Cout + (size_t)(row + 8) * ldc + col) = make_float2(v10, v11);
        }
}

// =============== cp.async plain-TF32 GEMM (pre-rounded inputs; GEMM4) ==========
template<int MODE>
__global__ void __launch_bounds__(256, 2)
gemm_tf32_async_kernel(const float* __restrict__ A, const float* __restrict__ B,
                       const float* __restrict__ bias, float* __restrict__ C,
                       int M, int N, int K, int lda, int ldb, int ldc)
{
    extern __shared__ float sm[];
    constexpr int STAGE = ASZ + BSZ;

    const int tid  = threadIdx.x;
    const int wid  = tid >> 5;
    const int lane = tid & 31;
    const int g    = lane >> 2;
    const int tg   = lane & 3;
    const int wm0  = (wid >> 2) << 6;
    const int wn0  = (wid & 3) << 5;
    const int m0   = blockIdx.y << 7;
    const int n0   = blockIdx.x << 7;

    float acc[4][4][4];
#pragma unroll
    for (int i = 0; i < 4; i++)
#pragma unroll
        for (int j = 0; j < 4; j++)
#pragma unroll
            for (int q = 0; q < 4; q++) acc[i][j][q] = 0.0f;

    auto issue_stage = [&](int s, int k0) {
        float* As = sm + s * STAGE;
        float* Bs = As + ASZ;
#pragma unroll
        for (int i = 0; i < 4; i++) {
            int lin = tid + (i << 8);
            int arow = lin >> 3, acol = (lin & 7) << 2;
            cp_async16(As + arow * AST + acol, A + (size_t)(m0 + arow) * lda + k0 + acol);
            int brow = lin >> 5, bcol = (lin & 31) << 2;
            cp_async16(Bs + brow * BST + bcol, B + (size_t)(k0 + brow) * ldb + n0 + bcol);
        }
        asm volatile("cp.async.commit_group;");
    };

    auto compute = [&](int s) {
        const float* As = sm + s * STAGE;
        const float* Bs = As + ASZ;
#pragma unroll
        for (int j = 0; j < 4; j++) {
            const int kk = j << 3;
            uint32_t ah[4][4], bh[4][2];
#pragma unroll
            for (int nf = 0; nf < 4; nf++) {
                int bn = wn0 + (nf << 3) + g;
                bh[nf][0] = __float_as_uint(Bs[(kk + tg) * BST + bn]);
                bh[nf][1] = __float_as_uint(Bs[(kk + tg + 4) * BST + bn]);
            }
#pragma unroll
            for (int mf = 0; mf < 4; mf++) {
                int rm = (wm0 + (mf << 4) + g) * AST + kk + tg;
                ah[mf][0] = __float_as_uint(As[rm]);
                ah[mf][1] = __float_as_uint(As[rm + 8 * AST]);
                ah[mf][2] = __float_as_uint(As[rm + 4]);
                ah[mf][3] = __float_as_uint(As[rm + 8 * AST + 4]);
            }
#pragma unroll
            for (int mf = 0; mf < 4; mf++)
#pragma unroll
                for (int nf = 0; nf < 4; nf++)
                    mma8(acc[mf][nf], ah[mf], bh[nf]);
        }
    };

    const int nt = K >> 5;
    issue_stage(0, 0);
    if (nt > 1) issue_stage(1, 32);
    asm volatile("cp.async.wait_group 1;");
    __syncthreads();

    for (int t = 0; t < nt; t++) {
        compute(t % 3);
        if (t + 1 < nt) {
            if (t + 2 < nt) {
                issue_stage((t + 2) % 3, (t + 2) << 5);
                asm volatile("cp.async.wait_group 1;");
            } else {
                asm volatile("cp.async.wait_group 0;");
            }
            __syncthreads();
        }
    }

#pragma unroll
    for (int mf = 0; mf < 4; mf++)
#pragma unroll
        for (int nf = 0; nf < 4; nf++) {
            int row = m0 + wm0 + (mf << 4) + g;
            int col = n0 + wn0 + (nf << 3) + (tg << 1);
            float b0 = 0.0f, b1 = 0.0f;
            if (MODE >= 1) { b0 = bias[col]; b1 = bias[col + 1]; }
            *(float2*)(C + (size_t)row * ldc + col) =
                make_float2(acc[mf][nf][0] + b0, acc[mf][nf][1] + b1);
            *(float2*)(C + (size_t)(row + 8) * ldc + col) =
                make_float2(acc[mf][nf][2] + b0, acc[mf][nf][3] + b1);
        }
}

// =============== cp.async 3xTF32 GEMM (pre-split hi/lo; GEMM3/delta) ===========
template<int MODE>
__global__ void __launch_bounds__(256)
gemm_tf32x3_async_kernel(const float* __restrict__ A_hi, const float* __restrict__ A_lo,
                         const float* __restrict__ B_hi, const float* __restrict__ B_lo,
                         const float* __restrict__ bias, float* __restrict__ C,
                         int M, int N, int K, int lda, int ldb, int ldc)
{
    extern __shared__ float sm[];
    constexpr int STAGE = 2 * (ASZ + BSZ);

    const int tid  = threadIdx.x;
    const int wid  = tid >> 5;
    const int lane = tid & 31;
    const int g    = lane >> 2;
    const int tg   = lane & 3;
    const int wm0  = (wid >> 2) << 6;
    const int wn0  = (wid & 3) << 5;
    const int m0   = blockIdx.y << 7;
    const int n0   = blockIdx.x << 7;

    float acc[4][4][4];
#pragma unroll
    for (int i = 0; i < 4; i++)
#pragma unroll
        for (int j = 0; j < 4; j++)
#pragma unroll
            for (int q = 0; q < 4; q++) acc[i][j][q] = 0.0f;

    auto issue_stage = [&](int s, int k0) {
        float* As_h = sm + s * STAGE;
        float* As_l = As_h + ASZ;
        float* Bs_h = As_h + 2 * ASZ;
        float* Bs_l = Bs_h + BSZ;
#pragma unroll
        for (int i = 0; i < 4; i++) {
            int lin = tid + (i << 8);
            int arow = lin >> 3, acol = (lin & 7) << 2;
            size_t aoff = (size_t)(m0 + arow) * lda + k0 + acol;
            cp_async16(As_h + arow * AST + acol, A_hi + aoff);
            cp_async16(As_l + arow * AST + acol, A_lo + aoff);
            int brow = lin >> 5, bcol = (lin & 31) << 2;
            size_t boff = (size_t)(k0 + brow) * ldb + n0 + bcol;
            cp_async16(Bs_h + brow * BST + bcol, B_hi + boff);
            cp_async16(Bs_l + brow * BST + bcol, B_lo + boff);
        }
        asm volatile("cp.async.commit_group;");
    };

    auto compute = [&](int s) {
        const float* As_h = sm + s * STAGE;
        const float* As_l = As_h + ASZ;
        const float* Bs_h = As_h + 2 * ASZ;
        const float* Bs_l = Bs_h + BSZ;
#pragma unroll
        for (int j = 0; j < 4; j++) {
            const int kk = j << 3;
            uint32_t ah[4][4], al[4][4], bh[4][2], bl[4][2];
#pragma unroll
            for (int nf = 0; nf < 4; nf++) {
                int bn = wn0 + (nf << 3) + g;
                bh[nf][0] = __float_as_uint(Bs_h[(kk + tg) * BST + bn]);
                bh[nf][1] = __float_as_uint(Bs_h[(kk + tg + 4) * BST + bn]);
                bl[nf][0] = __float_as_uint(Bs_l[(kk + tg) * BST + bn]);
                bl[nf][1] = __float_as_uint(Bs_l[(kk + tg + 4) * BST + bn]);
            }
#pragma unroll
            for (int mf = 0; mf < 4; mf++) {
                int rm = (wm0 + (mf << 4) + g) * AST + kk + tg;
                ah[mf][0] = __float_as_uint(As_h[rm]);
                ah[mf][1] = __float_as_uint(As_h[rm + 8 * AST]);
                ah[mf][2] = __float_as_uint(As_h[rm + 4]);
                ah[mf][3] = __float_as_uint(As_h[rm + 8 * AST + 4]);
                al[mf][0] = __float_as_uint(As_l[rm]);
                al[mf][1] = __float_as_uint(As_l[rm + 8 * AST]);
                al[mf][2] = __float_as_uint(As_l[rm + 4]);
                al[mf][3] = __float_as_uint(As_l[rm + 8 * AST + 4]);
            }
#pragma unroll
            for (int mf = 0; mf < 4; mf++)
#pragma unroll
                for (int nf = 0; nf < 4; nf++) {
                    mma8(acc[mf][nf], ah[mf], bh[nf]);
                    mma8(acc[mf][nf], ah[mf], bl[nf]);
                    mma8(acc[mf][nf], al[mf], bh[nf]);
                }
        }
    };

    const int nt = K >> 5;
    issue_stage(0, 0);
    asm volatile("cp.async.wait_group 0;");
    __syncthreads();
    for (int t = 0; t < nt; t++) {
        if (t + 1 < nt) issue_stage((t + 1) & 1, (t + 1) << 5);
        compute(t & 1);
        if (t + 1 < nt) {
            asm volatile("cp.async.wait_group 0;");
            __syncthreads();
        }
    }

#pragma unroll
    for (int mf = 0; mf < 4; mf++)
#pragma unroll
        for (int nf = 0; nf < 4; nf++) {
            int row = m0 + wm0 + (mf << 4) + g;
            int col = n0 + wn0 + (nf << 3) + (tg << 1);
            float b0 = 0.0f, b1 = 0.0f;
            if (MODE >= 1) { b0 = bias[col]; b1 = bias[col + 1]; }
            float v00 = acc[mf][nf][0] + b0, v01 = acc[mf][nf][1] + b1;
            float v10 = acc[mf][nf][2] + b0, v11 = acc[mf][nf][3] + b1;
            if (MODE == 2) {
                v00 = softplus_f(v00); v01 = softplus_f(v01);
                v10 = softplus_f(v10); v11 = softplus_f(v11);
            }
            *(float2*)(C + (size_t)row * ldc + col) = make_float2(v00, v01);
            *(float2*)(C + (size_t)(row + 8) * ldc + col) = make_float2(v10, v11);
        }
}

// ---------------- pre-round / pre-split inputs into scratch --------------------
__global__ void pre_round_kernel(const float* __restrict__ x,
                                 const float* __restrict__ W_in,
                                 const float* __restrict__ W_out,
                                 const float* __restrict__ W_dt,
                                 float* __restrict__ xhi,  float* __restrict__ xlo,
                                 float* __restrict__ w1hi, float* __restrict__ w1lo,
                                 float* __restrict__ wres,
                                 float* __restrict__ wout,
                                 float* __restrict__ wdthi, float* __restrict__ wdtlo)
{
    const int NX  = LSEQ * DM / 4;
    const int NW  = DM * DIN / 4;
    const int NWO = DIN * DM / 4;
    const int NWD = DTR * DIN / 4;
    int i = blockIdx.x * blockDim.x + threadIdx.x;
    if (i < NX) {
        float4 v = ((const float4*)x)[i];
        float4 h = tf32_rna4(v);
        ((float4*)xhi)[i] = h;
        ((float4*)xlo)[i] = tf32_rna4(make_float4(v.x - h.x, v.y - h.y, v.z - h.z, v.w - h.w));
    } else if (i < NX + NW) {
        int j = i - NX;
        int r = j / (DIN / 4), c = j % (DIN / 4);
        float4 v = *(const float4*)(W_in + (size_t)r * (2 * DIN) + c * 4);
        float4 h = tf32_rna4(v);
        ((float4*)w1hi)[j] = h;
        ((float4*)w1lo)[j] = tf32_rna4(make_float4(v.x - h.x, v.y - h.y, v.z - h.z, v.w - h.w));
    } else if (i < NX + 2 * NW) {
        int j = i - NX - NW;
        int r = j / (DIN / 4), c = j % (DIN / 4);
        float4 v = *(const float4*)(W_in + (size_t)r * (2 * DIN) + DIN + c * 4);
        ((float4*)wres)[j] = tf32_rna4(v);
    } else if (i < NX + 2 * NW + NWO) {
        int j = i - NX - 2 * NW;
        ((float4*)wout)[j] = tf32_rna4(((const float4*)W_out)[j]);
    } else if (i < NX + 2 * NW + NWO + NWD) {
        int j = i - NX - 2 * NW - NWO;
        float4 v = ((const float4*)W_dt)[j];
        float4 h = tf32_rna4(v);
        ((float4*)wdthi)[j] = h;
        ((float4*)wdtlo)[j] = tf32_rna4(make_float4(v.x - h.x, v.y - h.y, v.z - h.z, v.w - h.w));
    }
}

// reduce split-K partials; also emit tf32 hi/lo of the result (for async GEMM3)
__global__ void reduce_split_kernel(const float* __restrict__ part, float* __restrict__ out,
                                    float* __restrict__ out_hi, float* __restrict__ out_lo,
                                    int total, int splits)
{
    int i = blockIdx.x * blockDim.x + threadIdx.x;
    if (i >= total) return;
    float s = 0.0f;
    for (int z = 0; z < splits; z++) s += part[(size_t)z * total + i];
    out[i] = s;
    float h = tf32_rna(s);
    out_hi[i] = h;
    out_lo[i] = tf32_rna(s - h);
}

// ---------------- depthwise causal conv + bias + swish (float4 over d) --------
__global__ void conv_swish_kernel(const float* __restrict__ xr,
                                  const float* __restrict__ cw,
                                  const float* __restrict__ cb,
                                  float* __restrict__ xi)
{
    int idx = blockIdx.x * blockDim.x + threadIdx.x;    // over (LSEQ/4)*(DIN/4)
    if (idx >= (LSEQ / 4) * (DIN / 4)) return;
    int tb = (idx / (DIN / 4)) << 2;
    int d4 = (idx % (DIN / 4)) << 2;

    float4 wq[4];
#pragma unroll
    for (int c = 0; c < 4; c++) wq[c] = *(const float4*)(cw + (d4 + c) * KCONV);
    float4 bias = *(const float4*)(cb + d4);

    float4 v[7];
#pragma unroll
    for (int k = 0; k < 7; k++) {
        int tt = tb - 3 + k;
        v[k] = (tt >= 0) ? *(const float4*)(xr + (size_t)tt * (2 * DIN) + d4)
                         : make_float4(0.f, 0.f, 0.f, 0.f);
    }
#pragma unroll
    for (int o = 0; o < 4; o++) {
        float4 r;
        float a0 = bias.x;
        a0 = fmaf(wq[0].x, v[o].x,     a0);
        a0 = fmaf(wq[0].y, v[o + 1].x, a0);
        a0 = fmaf(wq[0].z, v[o + 2].x, a0);
        a0 = fmaf(wq[0].w, v[o + 3].x, a0);
        r.x = swish_f(a0);
        float a1 = bias.y;
        a1 = fmaf(wq[1].x, v[o].y,     a1);
        a1 = fmaf(wq[1].y, v[o + 1].y, a1);
        a1 = fmaf(wq[1].z, v[o + 2].y, a1);
        a1 = fmaf(wq[1].w, v[o + 3].y, a1);
        r.y = swish_f(a1);
        float a2 = bias.z;
        a2 = fmaf(wq[2].x, v[o].z,     a2);
        a2 = fmaf(wq[2].y, v[o + 1].z, a2);
        a2 = fmaf(wq[2].z, v[o + 2].z, a2);
        a2 = fmaf(wq[2].w, v[o + 3].z, a2);
        r.z = swish_f(a2);
        float a3 = bias.w;
        a3 = fmaf(wq[3].x, v[o].w,     a3);
        a3 = fmaf(wq[3].y, v[o + 1].w, a3);
        a3 = fmaf(wq[3].z, v[o + 2].w, a3);
        a3 = fmaf(wq[3].w, v[o + 3].w, a3);
        r.w = swish_f(a3);
        *(float4*)(xi + (size_t)(tb + o) * DIN + d4) = r;
    }
}

// ---------------- coalesced suffix scan, R in [t][d] layout --------------------
__global__ void chunk_sum_kernel(const float* __restrict__ delta, float* __restrict__ S)
{
    int d = blockIdx.x * blockDim.x + threadIdx.x;
    int c = blockIdx.y;
    float s = 0.0f;
#pragma unroll 8
    for (int i = 0; i < CHK; i++)
        s += delta[(size_t)(c * CHK + i) * DIN + d];
    S[(size_t)c * DIN + d] = s;
}

// backward walk per chunk, writing R[t][d]; also zeroes yacc at the same offsets
__global__ void suffix_write_kernel(const float* __restrict__ delta,
                                    const float* __restrict__ S,
                                    float* __restrict__ R,
                                    float* __restrict__ yacc)
{
    int d = blockIdx.x * blockDim.x + threadIdx.x;
    int c = blockIdx.y;
    float carry = 0.0f;
#pragma unroll
    for (int c2 = 0; c2 < NCHK; c2++)
        if (c2 > c) carry += S[(size_t)c2 * DIN + d];
    for (int i = CHK - 1; i >= 0; i--) {
        size_t off = (size_t)(c * CHK + i) * DIN + d;
        R[off] = carry;
        yacc[off] = 0.0f;
        carry += delta[off];
    }
}

// ---------------- sparse scan, n-major lanes (coalesced over d) ----------------
// Thread gI = n*DIN + d: a warp = 32 consecutive channels at a FIXED state n.
// All per-(t,d) loads are coalesced; Bn/Cn are warp-uniform broadcasts; atomics
// hit 32 distinct consecutive addresses. Lanes before their own live start
// compute exact zeros (w underflows -> c=0 -> xs=0 -> +0), matching the
// reference's underflow region, so warp lockstep from each lane's own lo is
// faithful (earlier-lo lanes just lead; laggards add zeros until t>=lo... note
// each lane simply starts at its own lo; divergence across a warp is small
// because live-window length depends mainly on n, which is warp-uniform).
__global__ void scan_sparse_kernel(const float* __restrict__ delta,
                                   const float* __restrict__ u,
                                   const float* __restrict__ xdbl,
                                   const float* __restrict__ A_log,
                                   const float* __restrict__ R,
                                   float* __restrict__ yacc)
{
    int gI = blockIdx.x * blockDim.x + threadIdx.x;   // 0..32767
    int n = gI >> 11;                                  // /DIN : fixed per warp
    int d = gI & (DIN - 1);
    float An = -fast_exp(A_log[(size_t)d * NST + n]);

    // own live start: first t with An*R[t][d] > -90  <=>  R < 90/(-An)
    float thresh = 90.0f / (-An);
    int lo = 0, hi = LSEQ;
    while (lo < hi) {
        int mid = (lo + hi) >> 1;
        if (R[(size_t)mid * DIN + d] < thresh) hi = mid; else lo = mid + 1;
    }
    // warp-min lo: lanes ahead of their own window compute exact zeros, and
    // lockstep keeps every load in the loop coalesced across the warp.
#pragma unroll
    for (int off = 16; off >= 1; off >>= 1)
        lo = min(lo, __shfl_xor_sync(0xffffffffu, lo, off));

    float c = 0.0f;
    for (int t = lo; t < LSEQ; t++) {
        size_t td = (size_t)t * DIN + d;
        float w  = fast_exp(An * R[td]);
        float de = delta[td];
        float uu = u[td];
        float Bn = xdbl[(size_t)t * XD + DTR + n];
        float Cn = xdbl[(size_t)t * XD + DTR + NST + n];
        c = fmaf(de * uu * Bn, w, c);
        float xs = c * fast_rcp(w + 1e-12f);
        atomicAdd(&yacc[td], xs * Cn);
    }
}

// ---------------- finalize (coalesced): y = tf32((yacc + u*D) * swish(res)) ----
__global__ void finalize_y_kernel(const float* __restrict__ yacc,
                                  const float* __restrict__ u,
                                  const float* __restrict__ xr,
                                  const float* __restrict__ Dv,
                                  float* __restrict__ y)
{
    int idx = blockIdx.x * blockDim.x + threadIdx.x;
    if (idx >= LSEQ * DIN) return;
    int t = idx >> 11;
    int d = idx & (DIN - 1);
    float res = xr[(size_t)t * (2 * DIN) + DIN + d];
    y[idx] = tf32_rna((yacc[idx] + u[idx] * Dv[d]) * swish_f(res));
}

// ---------------- launch ----------------
extern "C" void kernel_launch(void* const* d_in, const int* in_sizes, int n_in,
                              void* d_out, int out_size)
{
    const float* x      = (const float*)d_in[0];
    const float* W_in   = (const float*)d_in[1];
    const float* conv_w = (const float*)d_in[2];
    const float* conv_b = (const float*)d_in[3];
    const float* W_x    = (const float*)d_in[4];
    const float* W_dt   = (const float*)d_in[5];
    const float* b_dt   = (const float*)d_in[6];
    const float* A_log  = (const float*)d_in[7];
    const float* Dv     = (const float*)d_in[8];
    const float* W_out  = (const float*)d_in[9];
    const float* b_out  = (const float*)d_in[10];
    float* out = (float*)d_out;
    (void)in_sizes; (void)n_in; (void)out_size;

    float *xr, *xi, *xdbl, *xdbl_hi, *xdbl_lo, *delta, *Rbuf, *Sbuf, *yacc, *y, *part;
    float *xhi, *xlo, *w1hi, *w1lo, *wres, *wout, *wdthi, *wdtlo;
    cudaGetSymbolAddress((void**)&xr,      g_xr);
    cudaGetSymbolAddress((void**)&xi,      g_xi);
    cudaGetSymbolAddress((void**)&xdbl,    g_xdbl);
    cudaGetSymbolAddress((void**)&xdbl_hi, g_xdbl_hi);
    cudaGetSymbolAddress((void**)&xdbl_lo, g_xdbl_lo);
    cudaGetSymbolAddress((void**)&delta,   g_delta);
    cudaGetSymbolAddress((void**)&Rbuf,    g_R);
    cudaGetSymbolAddress((void**)&Sbuf,    g_S);
    cudaGetSymbolAddress((void**)&yacc,    g_yacc);
    cudaGetSymbolAddress((void**)&y,       g_y);
    cudaGetSymbolAddress((void**)&part,    g_part);
    cudaGetSymbolAddress((void**)&xhi,     g_xhi);
    cudaGetSymbolAddress((void**)&xlo,     g_xlo);
    cudaGetSymbolAddress((void**)&w1hi,    g_w1hi);
    cudaGetSymbolAddress((void**)&w1lo,    g_w1lo);
    cudaGetSymbolAddress((void**)&wres,    g_wres);
    cudaGetSymbolAddress((void**)&wout,    g_wout);
    cudaGetSymbolAddress((void**)&wdthi,   g_wdthi);
    cudaGetSymbolAddress((void**)&wdtlo,   g_wdtlo);

    const int SMEM3 = 2 * 2 * (ASZ + BSZ) * 4;   // 143360 B
    const int SMEMA = 3 * (ASZ + BSZ) * 4;       // 107520 B
    cudaFuncSetAttribute(gemm1_fused_kernel,
                         cudaFuncAttributeMaxDynamicSharedMemorySize, SMEM3);
    cudaFuncSetAttribute(gemm_tf32_kernel<true, 0>,
                         cudaFuncAttributeMaxDynamicSharedMemorySize, SMEM3);
    cudaFuncSetAttribute(gemm_tf32x3_async_kernel<2>,
                         cudaFuncAttributeMaxDynamicSharedMemorySize, SMEM3);
    cudaFuncSetAttribute(gemm_tf32_async_kernel<1>,
                         cudaFuncAttributeMaxDynamicSharedMemorySize, SMEMA);

    dim3 blk(256);

    // 0) pre-round / pre-split x, W_in, W_out, W_dt into tf32 scratch
    {
        const int total = LSEQ * DM / 4 + 2 * (DM * DIN / 4) + DIN * DM / 4 + DTR * DIN / 4;
        pre_round_kernel<<<(total + 255) / 256, blk>>>(
            x, W_in, W_out, W_dt, xhi, xlo, w1hi, w1lo, wres, wout, wdthi, wdtlo);
    }

    // 1) FUSED: xi_raw (3xTF32) + res (plain TF32) in one 512-block launch
    gemm1_fused_kernel<<<dim3(32, LSEQ / 128), blk, SMEM3>>>(
        xhi, xlo, w1hi, w1lo, wres, xr);

    // 2) xi = swish(causal depthwise conv(xi_raw) + conv_b)  (float4 over d)
    conv_swish_kernel<<<((LSEQ / 4) * (DIN / 4) + 255) / 256, blk>>>(
        xr, conv_w, conv_b, xi);

    // 3) x_dbl = xi @ W_x  (2048 x 96 x 2048) — 3xTF32 reg-staged split-K=8
    gemm_tf32_kernel<true, 0><<<dim3(1, LSEQ / 128, 8), blk, SMEM3>>>(
        xi, W_x, nullptr, part, LSEQ, XD, DIN, DIN, XD, XD);
    reduce_split_kernel<<<(LSEQ * XD + 255) / 256, blk>>>(
        part, xdbl, xdbl_hi, xdbl_lo, LSEQ * XD, 8);

    // 4) delta = softplus(delta_r @ W_dt + b_dt) — 3xTF32 cp.async (pre-split)
    gemm_tf32x3_async_kernel<2><<<dim3(DIN / 128, LSEQ / 128), blk, SMEM3>>>(
        xdbl_hi, xdbl_lo, wdthi, wdtlo, b_dt, delta, LSEQ, DIN, DTR, XD, DIN, DIN);

    // 5) selective scan — coalesced suffix (+fused yacc zero) + n-major sparse + finalize
    chunk_sum_kernel<<<dim3(DIN / 256, NCHK), blk>>>(delta, Sbuf);
    suffix_write_kernel<<<dim3(DIN / 256, NCHK), blk>>>(delta, Sbuf, Rbuf, yacc);
    scan_sparse_kernel<<<(DIN * NST) / 256, blk>>>(delta, xi, xdbl, A_log, Rbuf, yacc);
    finalize_y_kernel<<<(LSEQ * DIN + 255) / 256, blk>>>(yacc, xi, xr, Dv, y);

    // 6) out = y @ W_out + b_out  — plain TF32 cp.async
    gemm_tf32_async_kernel<1><<<dim3(DM / 128, LSEQ / 128), blk, SMEMA>>>(
        y, wout, b_out, out, LSEQ, DM, DIN, DIN, DM, DM);
}

// round 16
// speedup vs baseline: 1.0201x; 1.0201x over previous
#include <cuda_runtime.h>
#include <cstddef>
#include <cstdint>

#define LSEQ 2048
#define DM   1024
#define DIN  2048
#define NST  16
#define DTR  64
#define XD   96     // DTR + 2*NST
#define KCONV 4
#define NCHK 8      // suffix-scan chunks
#define CHK  256    // timesteps per chunk

// ---------------- scratch (device globals; no allocation allowed) ----------------
__device__ float g_xr[(size_t)LSEQ * 2 * DIN];            // [xi_raw | res]
__device__ float g_xi[(size_t)LSEQ * DIN];                // conv+swish output (u)
__device__ float g_xdbl[(size_t)LSEQ * XD];               // delta_r | B | C
__device__ float g_xdbl_hi[(size_t)LSEQ * XD];
__device__ float g_xdbl_lo[(size_t)LSEQ * XD];
__device__ float g_delta[(size_t)LSEQ * DIN];
__device__ float g_R[(size_t)LSEQ * DIN];                 // suffix sums, [t][d] layout
__device__ float g_S[(size_t)NCHK * DIN];                 // per-chunk channel sums
__device__ float g_yacc[(size_t)LSEQ * DIN];              // scan C-projection accumulator
__device__ float g_y[(size_t)LSEQ * DIN];                 // gated scan output (tf32-rounded)
__device__ float g_part[(size_t)8 * LSEQ * XD];           // split-K partials for GEMM2
__device__ float g_xhi[(size_t)LSEQ * DM];                // tf32 hi of x
__device__ float g_xlo[(size_t)LSEQ * DM];                // tf32 lo of x
__device__ float g_w1hi[(size_t)DM * DIN];                // hi of W_in[:, :DIN]
__device__ float g_w1lo[(size_t)DM * DIN];                // lo of W_in[:, :DIN]
__device__ float g_wres[(size_t)DM * DIN];                // hi of W_in[:, DIN:]
__device__ float g_wout[(size_t)DIN * DM];                // hi of W_out
__device__ float g_wdthi[(size_t)DTR * DIN];              // hi of W_dt
__device__ float g_wdtlo[(size_t)DTR * DIN];              // lo of W_dt

// ---------------- helpers ----------------
__device__ __forceinline__ float fast_exp(float x) {
    float y;
    asm("ex2.approx.f32 %0, %1;" : "=f"(y) : "f"(x * 1.4426950408889634f));
    return y;
}
__device__ __forceinline__ float fast_rcp(float x) {
    float y;
    asm("rcp.approx.f32 %0, %1;" : "=f"(y) : "f"(x));
    return y;
}
__device__ __forceinline__ float swish_f(float v) {
    return v / (1.0f + fast_exp(-v));
}
__device__ __forceinline__ float softplus_f(float v) {
    return log1pf(fast_exp(-fabsf(v))) + fmaxf(v, 0.0f);
}
__device__ __forceinline__ float tf32_rna(float x) {
    uint32_t u;
    asm("cvt.rna.tf32.f32 %0, %1;" : "=r"(u) : "f"(x));
    return __uint_as_float(u);
}
__device__ __forceinline__ float4 tf32_rna4(float4 v) {
    return make_float4(tf32_rna(v.x), tf32_rna(v.y), tf32_rna(v.z), tf32_rna(v.w));
}
__device__ __forceinline__ void mma8(float* d, const uint32_t* a, const uint32_t* b) {
    asm volatile("mma.sync.aligned.m16n8k8.row.col.f32.tf32.tf32.f32 "
        "{%0,%1,%2,%3}, {%4,%5,%6,%7}, {%8,%9}, {%0,%1,%2,%3};"
        : "+f"(d[0]), "+f"(d[1]), "+f"(d[2]), "+f"(d[3])
        : "r"(a[0]), "r"(a[1]), "r"(a[2]), "r"(a[3]), "r"(b[0]), "r"(b[1]));
}
__device__ __forceinline__ void cp_async16(void* smem_dst, const void* gsrc) {
    uint32_t d = (uint32_t)__cvta_generic_to_shared(smem_dst);
    asm volatile("cp.async.ca.shared.global [%0], [%1], 16;" :: "r"(d), "l"(gsrc));
}

constexpr int AST = 36;
constexpr int BST = 136;
constexpr int ASZ = 128 * AST;
constexpr int BSZ = 32 * BST;

// =============== FUSED GEMM1: xi_raw (3xTF32) + res (plain TF32), one launch ===
__global__ void __launch_bounds__(256)
gemm1_fused_kernel(const float* __restrict__ xhi, const float* __restrict__ xlo,
                   const float* __restrict__ w1hi, const float* __restrict__ w1lo,
                   const float* __restrict__ wres, float* __restrict__ xr)
{
    extern __shared__ float sm[];
    const int tid  = threadIdx.x;
    const int wid  = tid >> 5;
    const int lane = tid & 31;
    const int g    = lane >> 2;
    const int tg   = lane & 3;
    const int wm0  = (wid >> 2) << 6;
    const int wn0  = (wid & 3) << 5;
    const int m0   = blockIdx.y << 7;
    const bool three = (blockIdx.x < 16);
    const int n0   = (three ? blockIdx.x : (blockIdx.x - 16)) << 7;
    const int cbase = three ? 0 : DIN;

    float acc[4][4][4];
#pragma unroll
    for (int i = 0; i < 4; i++)
#pragma unroll
        for (int j = 0; j < 4; j++)
#pragma unroll
            for (int q = 0; q < 4; q++) acc[i][j][q] = 0.0f;

    const int nt = DM >> 5;   // 32 k-tiles

    if (three) {
        constexpr int STAGE = 2 * (ASZ + BSZ);
        auto issue_stage = [&](int s, int k0) {
            float* As_h = sm + s * STAGE;
            float* As_l = As_h + ASZ;
            float* Bs_h = As_h + 2 * ASZ;
            float* Bs_l = Bs_h + BSZ;
#pragma unroll
            for (int i = 0; i < 4; i++) {
                int lin = tid + (i << 8);
                int arow = lin >> 3, acol = (lin & 7) << 2;
                size_t aoff = (size_t)(m0 + arow) * DM + k0 + acol;
                cp_async16(As_h + arow * AST + acol, xhi + aoff);
                cp_async16(As_l + arow * AST + acol, xlo + aoff);
                int brow = lin >> 5, bcol = (lin & 31) << 2;
                size_t boff = (size_t)(k0 + brow) * DIN + n0 + bcol;
                cp_async16(Bs_h + brow * BST + bcol, w1hi + boff);
                cp_async16(Bs_l + brow * BST + bcol, w1lo + boff);
            }
            asm volatile("cp.async.commit_group;");
        };
        auto compute = [&](int s) {
            const float* As_h = sm + s * STAGE;
            const float* As_l = As_h + ASZ;
            const float* Bs_h = As_h + 2 * ASZ;
            const float* Bs_l = Bs_h + BSZ;
#pragma unroll
            for (int j = 0; j < 4; j++) {
                const int kk = j << 3;
                uint32_t ah[4][4], al[4][4], bh[4][2], bl[4][2];
#pragma unroll
                for (int nf = 0; nf < 4; nf++) {
                    int bn = wn0 + (nf << 3) + g;
                    bh[nf][0] = __float_as_uint(Bs_h[(kk + tg) * BST + bn]);
                    bh[nf][1] = __float_as_uint(Bs_h[(kk + tg + 4) * BST + bn]);
                    bl[nf][0] = __float_as_uint(Bs_l[(kk + tg) * BST + bn]);
                    bl[nf][1] = __float_as_uint(Bs_l[(kk + tg + 4) * BST + bn]);
                }
#pragma unroll
                for (int mf = 0; mf < 4; mf++) {
                    int rm = (wm0 + (mf << 4) + g) * AST + kk + tg;
                    ah[mf][0] = __float_as_uint(As_h[rm]);
                    ah[mf][1] = __float_as_uint(As_h[rm + 8 * AST]);
                    ah[mf][2] = __float_as_uint(As_h[rm + 4]);
                    ah[mf][3] = __float_as_uint(As_h[rm + 8 * AST + 4]);
                    al[mf][0] = __float_as_uint(As_l[rm]);
                    al[mf][1] = __float_as_uint(As_l[rm + 8 * AST]);
                    al[mf][2] = __float_as_uint(As_l[rm + 4]);
                    al[mf][3] = __float_as_uint(As_l[rm + 8 * AST + 4]);
                }
#pragma unroll
                for (int mf = 0; mf < 4; mf++)
#pragma unroll
                    for (int nf = 0; nf < 4; nf++) {
                        mma8(acc[mf][nf], ah[mf], bh[nf]);
                        mma8(acc[mf][nf], ah[mf], bl[nf]);
                        mma8(acc[mf][nf], al[mf], bh[nf]);
                    }
            }
        };
        issue_stage(0, 0);
        asm volatile("cp.async.wait_group 0;");
        __syncthreads();
        for (int t = 0; t < nt; t++) {
            if (t + 1 < nt) issue_stage((t + 1) & 1, (t + 1) << 5);
            compute(t & 1);
            if (t + 1 < nt) {
                asm volatile("cp.async.wait_group 0;");
                __syncthreads();
            }
        }
    } else {
        constexpr int STAGE = ASZ + BSZ;
        auto issue_stage = [&](int s, int k0) {
            float* As = sm + s * STAGE;
            float* Bs = As + ASZ;
#pragma unroll
            for (int i = 0; i < 4; i++) {
                int lin = tid + (i << 8);
                int arow = lin >> 3, acol = (lin & 7) << 2;
                cp_async16(As + arow * AST + acol, xhi + (size_t)(m0 + arow) * DM + k0 + acol);
                int brow = lin >> 5, bcol = (lin & 31) << 2;
                cp_async16(Bs + brow * BST + bcol, wres + (size_t)(k0 + brow) * DIN + n0 + bcol);
            }
            asm volatile("cp.async.commit_group;");
        };
        auto compute = [&](int s) {
            const float* As = sm + s * STAGE;
            const float* Bs = As + ASZ;
#pragma unroll
            for (int j = 0; j < 4; j++) {
                const int kk = j << 3;
                uint32_t ah[4][4], bh[4][2];
#pragma unroll
                for (int nf = 0; nf < 4; nf++) {
                    int bn = wn0 + (nf << 3) + g;
                    bh[nf][0] = __float_as_uint(Bs[(kk + tg) * BST + bn]);
                    bh[nf][1] = __float_as_uint(Bs[(kk + tg + 4) * BST + bn]);
                }
#pragma unroll
                for (int mf = 0; mf < 4; mf++) {
                    int rm = (wm0 + (mf << 4) + g) * AST + kk + tg;
                    ah[mf][0] = __float_as_uint(As[rm]);
                    ah[mf][1] = __float_as_uint(As[rm + 8 * AST]);
                    ah[mf][2] = __float_as_uint(As[rm + 4]);
                    ah[mf][3] = __float_as_uint(As[rm + 8 * AST + 4]);
                }
#pragma unroll
                for (int mf = 0; mf < 4; mf++)
#pragma unroll
                    for (int nf = 0; nf < 4; nf++)
                        mma8(acc[mf][nf], ah[mf], bh[nf]);
            }
        };
        issue_stage(0, 0);
        issue_stage(1, 32);
        asm volatile("cp.async.wait_group 1;");
        __syncthreads();
        for (int t = 0; t < nt; t++) {
            compute(t % 3);
            if (t + 1 < nt) {
                if (t + 2 < nt) {
                    issue_stage((t + 2) % 3, (t + 2) << 5);
                    asm volatile("cp.async.wait_group 1;");
                } else {
                    asm volatile("cp.async.wait_group 0;");
                }
                __syncthreads();
            }
        }
    }

#pragma unroll
    for (int mf = 0; mf < 4; mf++)
#pragma unroll
        for (int nf = 0; nf < 4; nf++) {
            int row = m0 + wm0 + (mf << 4) + g;
            int col = cbase + n0 + wn0 + (nf << 3) + (tg << 1);
            *(float2*)(xr + (size_t)row * (2 * DIN) + col) =
                make_float2(acc[mf][nf][0], acc[mf][nf][1]);
            *(float2*)(xr + (size_t)(row + 8) * (2 * DIN) + col) =
                make_float2(acc[mf][nf][2], acc[mf][nf][3]);
        }
}

// =============== 3xTF32 tensor GEMM (register-staged; measured-good GEMM2) =====
template<bool THREE, int MODE>
__global__ void __launch_bounds__(256)
gemm_tf32_kernel(const float* __restrict__ A, const float* __restrict__ B,
                 const float* __restrict__ bias, float* __restrict__ C,
                 int M, int N, int K, int lda, int ldb, int ldc)
{
    extern __shared__ float sm[];
    constexpr int STAGE = THREE ? 2 * (ASZ + BSZ) : (ASZ + BSZ);

    const int tid  = threadIdx.x;
    const int wid  = tid >> 5;
    const int lane = tid & 31;
    const int g    = lane >> 2;
    const int tg   = lane & 3;
    const int wm0  = (wid >> 2) << 6;
    const int wn0  = (wid & 3) << 5;
    const int m0   = blockIdx.y << 7;
    const int n0   = blockIdx.x << 7;

    const int splits = gridDim.z;
    const int Kc = K / splits;
    const int kbeg = blockIdx.z * Kc;

    float acc[4][4][4];
#pragma unroll
    for (int i = 0; i < 4; i++)
#pragma unroll
        for (int j = 0; j < 4; j++)
#pragma unroll
            for (int q = 0; q < 4; q++) acc[i][j][q] = 0.0f;

    float4 ra[4], rb[4];

    auto ldg_tile = [&](int k0) {
#pragma unroll
        for (int i = 0; i < 4; i++) {
            int lin = tid + (i << 8);
            ra[i] = *(const float4*)(A + (size_t)(m0 + (lin >> 3)) * lda + k0 + ((lin & 7) << 2));
            int gn = n0 + ((lin & 31) << 2);
            if (gn + 3 < N)
                rb[i] = *(const float4*)(B + (size_t)(k0 + (lin >> 5)) * ldb + gn);
            else
                rb[i] = make_float4(0.f, 0.f, 0.f, 0.f);
        }
    };

    auto sts_tile = [&](int s) {
        float* As_h = sm + s * STAGE;
        float* Bs_h = As_h + (THREE ? 2 * ASZ : ASZ);
#pragma unroll
        for (int i = 0; i < 4; i++) {
            int lin = tid + (i << 8);
            int arow = lin >> 3, acol = (lin & 7) << 2;
            float4 h = tf32_rna4(ra[i]);
            *(float4*)(As_h + arow * AST + acol) = h;
            if (THREE) {
                float4 l;
                l.x = tf32_rna(ra[i].x - h.x); l.y = tf32_rna(ra[i].y - h.y);
                l.z = tf32_rna(ra[i].z - h.z); l.w = tf32_rna(ra[i].w - h.w);
                *(float4*)(As_h + ASZ + arow * AST + acol) = l;
            }
            int brow = lin >> 5, bcol = (lin & 31) << 2;
            float4 bh = tf32_rna4(rb[i]);
            *(float4*)(Bs_h + brow * BST + bcol) = bh;
            if (THREE) {
                float4 bl;
                bl.x = tf32_rna(rb[i].x - bh.x); bl.y = tf32_rna(rb[i].y - bh.y);
                bl.z = tf32_rna(rb[i].z - bh.z); bl.w = tf32_rna(rb[i].w - bh.w);
                *(float4*)(Bs_h + BSZ + brow * BST + bcol) = bl;
            }
        }
    };

    auto compute = [&](int s) {
        const float* As_h = sm + s * STAGE;
        const float* As_l = As_h + ASZ;
        const float* Bs_h = As_h + (THREE ? 2 * ASZ : ASZ);
        const float* Bs_l = Bs_h + BSZ;
#pragma unroll
        for (int j = 0; j < 4; j++) {
            const int kk = j << 3;
            uint32_t ah[4][4], bh[4][2];
            uint32_t al[4][4], bl[4][2];
#pragma unroll
            for (int nf = 0; nf < 4; nf++) {
                int bn = wn0 + (nf << 3) + g;
                bh[nf][0] = __float_as_uint(Bs_h[(kk + tg) * BST + bn]);
                bh[nf][1] = __float_as_uint(Bs_h[(kk + tg + 4) * BST + bn]);
                if (THREE) {
                    bl[nf][0] = __float_as_uint(Bs_l[(kk + tg) * BST + bn]);
                    bl[nf][1] = __float_as_uint(Bs_l[(kk + tg + 4) * BST + bn]);
                }
            }
#pragma unroll
            for (int mf = 0; mf < 4; mf++) {
                int rm = (wm0 + (mf << 4) + g) * AST + kk + tg;
                ah[mf][0] = __float_as_uint(As_h[rm]);
                ah[mf][1] = __float_as_uint(As_h[rm + 8 * AST]);
                ah[mf][2] = __float_as_uint(As_h[rm + 4]);
                ah[mf][3] = __float_as_uint(As_h[rm + 8 * AST + 4]);
                if (THREE) {
                    al[mf][0] = __float_as_uint(As_l[rm]);
                    al[mf][1] = __float_as_uint(As_l[rm + 8 * AST]);
                    al[mf][2] = __float_as_uint(As_l[rm + 4]);
                    al[mf][3] = __float_as_uint(As_l[rm + 8 * AST + 4]);
                }
            }
#pragma unroll
            for (int mf = 0; mf < 4; mf++)
#pragma unroll
                for (int nf = 0; nf < 4; nf++) {
                    mma8(acc[mf][nf], ah[mf], bh[nf]);
                    if (THREE) {
                        mma8(acc[mf][nf], ah[mf], bl[nf]);
                        mma8(acc[mf][nf], al[mf], bh[nf]);
                    }
                }
        }
    };

    const int nt = Kc >> 5;
    ldg_tile(kbeg);
    sts_tile(0);
    __syncthreads();
    for (int t = 0; t < nt; t++) {
        if (t + 1 < nt) ldg_tile(kbeg + ((t + 1) << 5));
        compute(t & 1);
        if (t + 1 < nt) {
            __syncthreads();
            sts_tile((t + 1) & 1);
            __syncthreads();
        }
    }

    float* Cout = C + (size_t)blockIdx.z * M * ldc;

#pragma unroll
    for (int mf = 0; mf < 4; mf++)
#pragma unroll
        for (int nf = 0; nf < 4; nf++) {
            int row = m0 + wm0 + (mf << 4) + g;
            int col = n0 + wn0 + (nf << 3) + (tg << 1);
            if (col + 1 >= N) continue;
            float b0 = 0.0f, b1 = 0.0f;
            if (MODE >= 1 && splits == 1) { b0 = bias[col]; b1 = bias[col + 1]; }
            float v00 = acc[mf][nf][0] + b0, v01 = acc[mf][nf][1] + b1;
            float v10 = acc[mf][nf][2] + b0, v11 = acc[mf][nf][3] + b1;
            if (MODE == 2 && splits == 1) {
                v00 = softplus_f(v00); v01 = softplus_f(v01);
                v10 = softplus_f(v10); v11 = softplus_f(v11);
            }
            *(float2*)(Cout + (size_t)row * ldc + col) = make_float2(v00, v01);
            *(float2*)(Cout + (size_t)(row + 8) * ldc + col) = make_float2(v10, v11);
        }
}

// =============== cp.async plain-TF32 GEMM (pre-rounded inputs; GEMM4) ==========
template<int MODE>
__global__ void __launch_bounds__(256, 2)
gemm_tf32_async_kernel(const float* __restrict__ A, const float* __restrict__ B,
                       const float* __restrict__ bias, float* __restrict__ C,
                       int M, int N, int K, int lda, int ldb, int ldc)
{
    extern __shared__ float sm[];
    constexpr int STAGE = ASZ + BSZ;

    const int tid  = threadIdx.x;
    const int wid  = tid >> 5;
    const int lane = tid & 31;
    const int g    = lane >> 2;
    const int tg   = lane & 3;
    const int wm0  = (wid >> 2) << 6;
    const int wn0  = (wid & 3) << 5;
    const int m0   = blockIdx.y << 7;
    const int n0   = blockIdx.x << 7;

    float acc[4][4][4];
#pragma unroll
    for (int i = 0; i < 4; i++)
#pragma unroll
        for (int j = 0; j < 4; j++)
#pragma unroll
            for (int q = 0; q < 4; q++) acc[i][j][q] = 0.0f;

    auto issue_stage = [&](int s, int k0) {
        float* As = sm + s * STAGE;
        float* Bs = As + ASZ;
#pragma unroll
        for (int i = 0; i < 4; i++) {
            int lin = tid + (i << 8);
            int arow = lin >> 3, acol = (lin & 7) << 2;
            cp_async16(As + arow * AST + acol, A + (size_t)(m0 + arow) * lda + k0 + acol);
            int brow = lin >> 5, bcol = (lin & 31) << 2;
            cp_async16(Bs + brow * BST + bcol, B + (size_t)(k0 + brow) * ldb + n0 + bcol);
        }
        asm volatile("cp.async.commit_group;");
    };

    auto compute = [&](int s) {
        const float* As = sm + s * STAGE;
        const float* Bs = As + ASZ;
#pragma unroll
        for (int j = 0; j < 4; j++) {
            const int kk = j << 3;
            uint32_t ah[4][4], bh[4][2];
#pragma unroll
            for (int nf = 0; nf < 4; nf++) {
                int bn = wn0 + (nf << 3) + g;
                bh[nf][0] = __float_as_uint(Bs[(kk + tg) * BST + bn]);
                bh[nf][1] = __float_as_uint(Bs[(kk + tg + 4) * BST + bn]);
            }
#pragma unroll
            for (int mf = 0; mf < 4; mf++) {
                int rm = (wm0 + (mf << 4) + g) * AST + kk + tg;
                ah[mf][0] = __float_as_uint(As[rm]);
                ah[mf][1] = __float_as_uint(As[rm + 8 * AST]);
                ah[mf][2] = __float_as_uint(As[rm + 4]);
                ah[mf][3] = __float_as_uint(As[rm + 8 * AST + 4]);
            }
#pragma unroll
            for (int mf = 0; mf < 4; mf++)
#pragma unroll
                for (int nf = 0; nf < 4; nf++)
                    mma8(acc[mf][nf], ah[mf], bh[nf]);
        }
    };

    const int nt = K >> 5;
    issue_stage(0, 0);
    if (nt > 1) issue_stage(1, 32);
    asm volatile("cp.async.wait_group 1;");
    __syncthreads();

    for (int t = 0; t < nt; t++) {
        compute(t % 3);
        if (t + 1 < nt) {
            if (t + 2 < nt) {
                issue_stage((t + 2) % 3, (t + 2) << 5);
                asm volatile("cp.async.wait_group 1;");
            } else {
                asm volatile("cp.async.wait_group 0;");
            }
            __syncthreads();
        }
    }

#pragma unroll
    for (int mf = 0; mf < 4; mf++)
#pragma unroll
        for (int nf = 0; nf < 4; nf++) {
            int row = m0 + wm0 + (mf << 4) + g;
            int col = n0 + wn0 + (nf << 3) + (tg << 1);
            float b0 = 0.0f, b1 = 0.0f;
            if (MODE >= 1) { b0 = bias[col]; b1 = bias[col + 1]; }
            *(float2*)(C + (size_t)row * ldc + col) =
                make_float2(acc[mf][nf][0] + b0, acc[mf][nf][1] + b1);
            *(float2*)(C + (size_t)(row + 8) * ldc + col) =
                make_float2(acc[mf][nf][2] + b0, acc[mf][nf][3] + b1);
        }
}

// =============== cp.async 3xTF32 GEMM (pre-split hi/lo; GEMM3/delta) ===========
template<int MODE>
__global__ void __launch_bounds__(256)
gemm_tf32x3_async_kernel(const float* __restrict__ A_hi, const float* __restrict__ A_lo,
                         const float* __restrict__ B_hi, const float* __restrict__ B_lo,
                         const float* __restrict__ bias, float* __restrict__ C,
                         int M, int N, int K, int lda, int ldb, int ldc)
{
    extern __shared__ float sm[];
    constexpr int STAGE = 2 * (ASZ + BSZ);

    const int tid  = threadIdx.x;
    const int wid  = tid >> 5;
    const int lane = tid & 31;
    const int g    = lane >> 2;
    const int tg   = lane & 3;
    const int wm0  = (wid >> 2) << 6;
    const int wn0  = (wid & 3) << 5;
    const int m0   = blockIdx.y << 7;
    const int n0   = blockIdx.x << 7;

    float acc[4][4][4];
#pragma unroll
    for (int i = 0; i < 4; i++)
#pragma unroll
        for (int j = 0; j < 4; j++)
#pragma unroll
            for (int q = 0; q < 4; q++) acc[i][j][q] = 0.0f;

    auto issue_stage = [&](int s, int k0) {
        float* As_h = sm + s * STAGE;
        float* As_l = As_h + ASZ;
        float* Bs_h = As_h + 2 * ASZ;
        float* Bs_l = Bs_h + BSZ;
#pragma unroll
        for (int i = 0; i < 4; i++) {
            int lin = tid + (i << 8);
            int arow = lin >> 3, acol = (lin & 7) << 2;
            size_t aoff = (size_t)(m0 + arow) * lda + k0 + acol;
            cp_async16(As_h + arow * AST + acol, A_hi + aoff);
            cp_async16(As_l + arow * AST + acol, A_lo + aoff);
            int brow = lin >> 5, bcol = (lin & 31) << 2;
            size_t boff = (size_t)(k0 + brow) * ldb + n0 + bcol;
            cp_async16(Bs_h + brow * BST + bcol, B_hi + boff);
            cp_async16(Bs_l + brow * BST + bcol, B_lo + boff);
        }
        asm volatile("cp.async.commit_group;");
    };

    auto compute = [&](int s) {
        const float* As_h = sm + s * STAGE;
        const float* As_l = As_h + ASZ;
        const float* Bs_h = As_h + 2 * ASZ;
        const float* Bs_l = Bs_h + BSZ;
#pragma unroll
        for (int j = 0; j < 4; j++) {
            const int kk = j << 3;
            uint32_t ah[4][4], al[4][4], bh[4][2], bl[4][2];
#pragma unroll
            for (int nf = 0; nf < 4; nf++) {
                int bn = wn0 + (nf << 3) + g;
                bh[nf][0] = __float_as_uint(Bs_h[(kk + tg) * BST + bn]);
                bh[nf][1] = __float_as_uint(Bs_h[(kk + tg + 4) * BST + bn]);
                bl[nf][0] = __float_as_uint(Bs_l[(kk + tg) * BST + bn]);
                bl[nf][1] = __float_as_uint(Bs_l[(kk + tg + 4) * BST + bn]);
            }
#pragma unroll
            for (int mf = 0; mf < 4; mf++) {
                int rm = (wm0 + (mf << 4) + g) * AST + kk + tg;
                ah[mf][0] = __float_as_uint(As_h[rm]);
                ah[mf][1] = __float_as_uint(As_h[rm + 8 * AST]);
                ah[mf][2] = __float_as_uint(As_h[rm + 4]);
                ah[mf][3] = __float_as_uint(As_h[rm + 8 * AST + 4]);
                al[mf][0] = __float_as_uint(As_l[rm]);
                al[mf][1] = __float_as_uint(As_l[rm + 8 * AST]);
                al[mf][2] = __float_as_uint(As_l[rm + 4]);
                al[mf][3] = __float_as_uint(As_l[rm + 8 * AST + 4]);
            }
#pragma unroll
            for (int mf = 0; mf < 4; mf++)
#pragma unroll
                for (int nf = 0; nf < 4; nf++) {
                    mma8(acc[mf][nf], ah[mf], bh[nf]);
                    mma8(acc[mf][nf], ah[mf], bl[nf]);
                    mma8(acc[mf][nf], al[mf], bh[nf]);
                }
        }
    };

    const int nt = K >> 5;
    issue_stage(0, 0);
    asm volatile("cp.async.wait_group 0;");
    __syncthreads();
    for (int t = 0; t < nt; t++) {
        if (t + 1 < nt) issue_stage((t + 1) & 1, (t + 1) << 5);
        compute(t & 1);
        if (t + 1 < nt) {
            asm volatile("cp.async.wait_group 0;");
            __syncthreads();
        }
    }

#pragma unroll
    for (int mf = 0; mf < 4; mf++)
#pragma unroll
        for (int nf = 0; nf < 4; nf++) {
            int row = m0 + wm0 + (mf << 4) + g;
            int col = n0 + wn0 + (nf << 3) + (tg << 1);
            float b0 = 0.0f, b1 = 0.0f;
            if (MODE >= 1) { b0 = bias[col]; b1 = bias[col + 1]; }
            float v00 = acc[mf][nf][0] + b0, v01 = acc[mf][nf][1] + b1;
            float v10 = acc[mf][nf][2] + b0, v11 = acc[mf][nf][3] + b1;
            if (MODE == 2) {
                v00 = softplus_f(v00); v01 = softplus_f(v01);
                v10 = softplus_f(v10); v11 = softplus_f(v11);
            }
            *(float2*)(C + (size_t)row * ldc + col) = make_float2(v00, v01);
            *(float2*)(C + (size_t)(row + 8) * ldc + col) = make_float2(v10, v11);
        }
}

// ---------------- pre-round / pre-split inputs into scratch --------------------
__global__ void pre_round_kernel(const float* __restrict__ x,
                                 const float* __restrict__ W_in,
                                 const float* __restrict__ W_out,
                                 const float* __restrict__ W_dt,
                                 float* __restrict__ xhi,  float* __restrict__ xlo,
                                 float* __restrict__ w1hi, float* __restrict__ w1lo,
                                 float* __restrict__ wres,
                                 float* __restrict__ wout,
                                 float* __restrict__ wdthi, float* __restrict__ wdtlo)
{
    const int NX  = LSEQ * DM / 4;
    const int NW  = DM * DIN / 4;
    const int NWO = DIN * DM / 4;
    const int NWD = DTR * DIN / 4;
    int i = blockIdx.x * blockDim.x + threadIdx.x;
    if (i < NX) {
        float4 v = ((const float4*)x)[i];
        float4 h = tf32_rna4(v);
        ((float4*)xhi)[i] = h;
        ((float4*)xlo)[i] = tf32_rna4(make_float4(v.x - h.x, v.y - h.y, v.z - h.z, v.w - h.w));
    } else if (i < NX + NW) {
        int j = i - NX;
        int r = j / (DIN / 4), c = j % (DIN / 4);
        float4 v = *(const float4*)(W_in + (size_t)r * (2 * DIN) + c * 4);
        float4 h = tf32_rna4(v);
        ((float4*)w1hi)[j] = h;
        ((float4*)w1lo)[j] = tf32_rna4(make_float4(v.x - h.x, v.y - h.y, v.z - h.z, v.w - h.w));
    } else if (i < NX + 2 * NW) {
        int j = i - NX - NW;
        int r = j / (DIN / 4), c = j % (DIN / 4);
        float4 v = *(const float4*)(W_in + (size_t)r * (2 * DIN) + DIN + c * 4);
        ((float4*)wres)[j] = tf32_rna4(v);
    } else if (i < NX + 2 * NW + NWO) {
        int j = i - NX - 2 * NW;
        ((float4*)wout)[j] = tf32_rna4(((const float4*)W_out)[j]);
    } else if (i < NX + 2 * NW + NWO + NWD) {
        int j = i - NX - 2 * NW - NWO;
        float4 v = ((const float4*)W_dt)[j];
        float4 h = tf32_rna4(v);
        ((float4*)wdthi)[j] = h;
        ((float4*)wdtlo)[j] = tf32_rna4(make_float4(v.x - h.x, v.y - h.y, v.z - h.z, v.w - h.w));
    }
}

// reduce split-K partials; also emit tf32 hi/lo of the result (for async GEMM3)
__global__ void reduce_split_kernel(const float* __restrict__ part, float* __restrict__ out,
                                    float* __restrict__ out_hi, float* __restrict__ out_lo,
                                    int total, int splits)
{
    int i = blockIdx.x * blockDim.x + threadIdx.x;
    if (i >= total) return;
    float s = 0.0f;
    for (int z = 0; z < splits; z++) s += part[(size_t)z * total + i];
    out[i] = s;
    float h = tf32_rna(s);
    out_hi[i] = h;
    out_lo[i] = tf32_rna(s - h);
}

// ---------------- depthwise causal conv + bias + swish (float4 over d) --------
__global__ void conv_swish_kernel(const float* __restrict__ xr,
                                  const float* __restrict__ cw,
                                  const float* __restrict__ cb,
                                  float* __restrict__ xi)
{
    int idx = blockIdx.x * blockDim.x + threadIdx.x;    // over (LSEQ/4)*(DIN/4)
    if (idx >= (LSEQ / 4) * (DIN / 4)) return;
    int tb = (idx / (DIN / 4)) << 2;
    int d4 = (idx % (DIN / 4)) << 2;

    float4 wq[4];
#pragma unroll
    for (int c = 0; c < 4; c++) wq[c] = *(const float4*)(cw + (d4 + c) * KCONV);
    float4 bias = *(const float4*)(cb + d4);

    float4 v[7];
#pragma unroll
    for (int k = 0; k < 7; k++) {
        int tt = tb - 3 + k;
        v[k] = (tt >= 0) ? *(const float4*)(xr + (size_t)tt * (2 * DIN) + d4)
                         : make_float4(0.f, 0.f, 0.f, 0.f);
    }
#pragma unroll
    for (int o = 0; o < 4; o++) {
        float4 r;
        float a0 = bias.x;
        a0 = fmaf(wq[0].x, v[o].x,     a0);
        a0 = fmaf(wq[0].y, v[o + 1].x, a0);
        a0 = fmaf(wq[0].z, v[o + 2].x, a0);
        a0 = fmaf(wq[0].w, v[o + 3].x, a0);
        r.x = swish_f(a0);
        float a1 = bias.y;
        a1 = fmaf(wq[1].x, v[o].y,     a1);
        a1 = fmaf(wq[1].y, v[o + 1].y, a1);
        a1 = fmaf(wq[1].z, v[o + 2].y, a1);
        a1 = fmaf(wq[1].w, v[o + 3].y, a1);
        r.y = swish_f(a1);
        float a2 = bias.z;
        a2 = fmaf(wq[2].x, v[o].z,     a2);
        a2 = fmaf(wq[2].y, v[o + 1].z, a2);
        a2 = fmaf(wq[2].z, v[o + 2].z, a2);
        a2 = fmaf(wq[2].w, v[o + 3].z, a2);
        r.z = swish_f(a2);
        float a3 = bias.w;
        a3 = fmaf(wq[3].x, v[o].w,     a3);
        a3 = fmaf(wq[3].y, v[o + 1].w, a3);
        a3 = fmaf(wq[3].z, v[o + 2].w, a3);
        a3 = fmaf(wq[3].w, v[o + 3].w, a3);
        r.w = swish_f(a3);
        *(float4*)(xi + (size_t)(tb + o) * DIN + d4) = r;
    }
}

// ---------------- coalesced suffix scan, R in [t][d] layout --------------------
__global__ void chunk_sum_kernel(const float* __restrict__ delta, float* __restrict__ S)
{
    int d = blockIdx.x * blockDim.x + threadIdx.x;
    int c = blockIdx.y;
    float s = 0.0f;
#pragma unroll 8
    for (int i = 0; i < CHK; i++)
        s += delta[(size_t)(c * CHK + i) * DIN + d];
    S[(size_t)c * DIN + d] = s;
}

// backward walk per chunk, writing R[t][d]; also zeroes yacc at the same offsets
__global__ void suffix_write_kernel(const float* __restrict__ delta,
                                    const float* __restrict__ S,
                                    float* __restrict__ R,
                                    float* __restrict__ yacc)
{
    int d = blockIdx.x * blockDim.x + threadIdx.x;
    int c = blockIdx.y;
    float carry = 0.0f;
#pragma unroll
    for (int c2 = 0; c2 < NCHK; c2++)
        if (c2 > c) carry += S[(size_t)c2 * DIN + d];
    for (int i = CHK - 1; i >= 0; i--) {
        size_t off = (size_t)(c * CHK + i) * DIN + d;
        R[off] = carry;
        yacc[off] = 0.0f;
        carry += delta[off];
    }
}

// ---------------- sparse scan (d-major own-window walk; measured-best R14) -----
__global__ void scan_sparse_kernel(const float* __restrict__ delta,
                                   const float* __restrict__ u,
                                   const float* __restrict__ xdbl,
                                   const float* __restrict__ A_log,
                                   const float* __restrict__ R,
                                   float* __restrict__ yacc)
{
    int gI = blockIdx.x * blockDim.x + threadIdx.x;   // 0..32767
    int d = gI >> 4;
    int n = gI & 15;
    float An = -fast_exp(A_log[gI]);

    float thresh = 90.0f / (-An);
    int lo = 0, hi = LSEQ;
    while (lo < hi) {
        int mid = (lo + hi) >> 1;
        if (R[(size_t)mid * DIN + d] < thresh) hi = mid; else lo = mid + 1;
    }

    float c = 0.0f;
    for (int t = lo; t < LSEQ; t++) {
        float w  = fast_exp(An * R[(size_t)t * DIN + d]);
        float de = delta[(size_t)t * DIN + d];
        float uu = u[(size_t)t * DIN + d];
        float Bn = xdbl[(size_t)t * XD + DTR + n];
        float Cn = xdbl[(size_t)t * XD + DTR + NST + n];
        c = fmaf(de * uu * Bn, w, c);
        float xs = c * fast_rcp(w + 1e-12f);
        atomicAdd(&yacc[(size_t)t * DIN + d], xs * Cn);
    }
}

// ---------------- finalize (float4): y = tf32((yacc + u*D) * swish(res)) -------
__global__ void finalize_y_kernel(const float* __restrict__ yacc,
                                  const float* __restrict__ u,
                                  const float* __restrict__ xr,
                                  const float* __restrict__ Dv,
                                  float* __restrict__ y)
{
    int idx = blockIdx.x * blockDim.x + threadIdx.x;   // over LSEQ*DIN/4
    if (idx >= LSEQ * DIN / 4) return;
    int t  = idx / (DIN / 4);
    int d4 = (idx % (DIN / 4)) << 2;

    float4 ya = ((const float4*)yacc)[idx];
    float4 uu = ((const float4*)u)[idx];
    float4 dd = *(const float4*)(Dv + d4);
    float4 rs = *(const float4*)(xr + (size_t)t * (2 * DIN) + DIN + d4);

    float4 r;
    r.x = tf32_rna((ya.x + uu.x * dd.x) * swish_f(rs.x));
    r.y = tf32_rna((ya.y + uu.y * dd.y) * swish_f(rs.y));
    r.z = tf32_rna((ya.z + uu.z * dd.z) * swish_f(rs.z));
    r.w = tf32_rna((ya.w + uu.w * dd.w) * swish_f(rs.w));
    ((float4*)y)[idx] = r;
}

// ---------------- launch ----------------
extern "C" void kernel_launch(void* const* d_in, const int* in_sizes, int n_in,
                              void* d_out, int out_size)
{
    const float* x      = (const float*)d_in[0];
    const float* W_in   = (const float*)d_in[1];
    const float* conv_w = (const float*)d_in[2];
    const float* conv_b = (const float*)d_in[3];
    const float* W_x    = (const float*)d_in[4];
    const float* W_dt   = (const float*)d_in[5];
    const float* b_dt   = (const float*)d_in[6];
    const float* A_log  = (const float*)d_in[7];
    const float* Dv     = (const float*)d_in[8];
    const float* W_out  = (const float*)d_in[9];
    const float* b_out  = (const float*)d_in[10];
    float* out = (float*)d_out;
    (void)in_sizes; (void)n_in; (void)out_size;

    float *xr, *xi, *xdbl, *xdbl_hi, *xdbl_lo, *delta, *Rbuf, *Sbuf, *yacc, *y, *part;
    float *xhi, *xlo, *w1hi, *w1lo, *wres, *wout, *wdthi, *wdtlo;
    cudaGetSymbolAddress((void**)&xr,      g_xr);
    cudaGetSymbolAddress((void**)&xi,      g_xi);
    cudaGetSymbolAddress((void**)&xdbl,    g_xdbl);
    cudaGetSymbolAddress((void**)&xdbl_hi, g_xdbl_hi);
    cudaGetSymbolAddress((void**)&xdbl_lo, g_xdbl_lo);
    cudaGetSymbolAddress((void**)&delta,   g_delta);
    cudaGetSymbolAddress((void**)&Rbuf,    g_R);
    cudaGetSymbolAddress((void**)&Sbuf,    g_S);
    cudaGetSymbolAddress((void**)&yacc,    g_yacc);
    cudaGetSymbolAddress((void**)&y,       g_y);
    cudaGetSymbolAddress((void**)&part,    g_part);
    cudaGetSymbolAddress((void**)&xhi,     g_xhi);
    cudaGetSymbolAddress((void**)&xlo,     g_xlo);
    cudaGetSymbolAddress((void**)&w1hi,    g_w1hi);
    cudaGetSymbolAddress((void**)&w1lo,    g_w1lo);
    cudaGetSymbolAddress((void**)&wres,    g_wres);
    cudaGetSymbolAddress((void**)&wout,    g_wout);
    cudaGetSymbolAddress((void**)&wdthi,   g_wdthi);
    cudaGetSymbolAddress((void**)&wdtlo,   g_wdtlo);

    const int SMEM3 = 2 * 2 * (ASZ + BSZ) * 4;   // 143360 B
    const int SMEMA = 3 * (ASZ + BSZ) * 4;       // 107520 B
    cudaFuncSetAttribute(gemm1_fused_kernel,
                         cudaFuncAttributeMaxDynamicSharedMemorySize, SMEM3);
    cudaFuncSetAttribute(gemm_tf32_kernel<true, 0>,
                         cudaFuncAttributeMaxDynamicSharedMemorySize, SMEM3);
    cudaFuncSetAttribute(gemm_tf32x3_async_kernel<2>,
                         cudaFuncAttributeMaxDynamicSharedMemorySize, SMEM3);
    cudaFuncSetAttribute(gemm_tf32_async_kernel<1>,
                         cudaFuncAttributeMaxDynamicSharedMemorySize, SMEMA);

    dim3 blk(256);

    // 0) pre-round / pre-split x, W_in, W_out, W_dt into tf32 scratch
    {
        const int total = LSEQ * DM / 4 + 2 * (DM * DIN / 4) + DIN * DM / 4 + DTR * DIN / 4;
        pre_round_kernel<<<(total + 255) / 256, blk>>>(
            x, W_in, W_out, W_dt, xhi, xlo, w1hi, w1lo, wres, wout, wdthi, wdtlo);
    }

    // 1) FUSED: xi_raw (3xTF32) + res (plain TF32) in one 512-block launch
    gemm1_fused_kernel<<<dim3(32, LSEQ / 128), blk, SMEM3>>>(
        xhi, xlo, w1hi, w1lo, wres, xr);

    // 2) xi = swish(causal depthwise conv(xi_raw) + conv_b)  (float4 over d)
    conv_swish_kernel<<<((LSEQ / 4) * (DIN / 4) + 255) / 256, blk>>>(
        xr, conv_w, conv_b, xi);

    // 3) x_dbl = xi @ W_x  (2048 x 96 x 2048) — 3xTF32 reg-staged split-K=8
    gemm_tf32_kernel<true, 0><<<dim3(1, LSEQ / 128, 8), blk, SMEM3>>>(
        xi, W_x, nullptr, part, LSEQ, XD, DIN, DIN, XD, XD);
    reduce_split_kernel<<<(LSEQ * XD + 255) / 256, blk>>>(
        part, xdbl, xdbl_hi, xdbl_lo, LSEQ * XD, 8);

    // 4) delta = softplus(delta_r @ W_dt + b_dt) — 3xTF32 cp.async (pre-split)
    gemm_tf32x3_async_kernel<2><<<dim3(DIN / 128, LSEQ / 128), blk, SMEM3>>>(
        xdbl_hi, xdbl_lo, wdthi, wdtlo, b_dt, delta, LSEQ, DIN, DTR, XD, DIN, DIN);

    // 5) selective scan — coalesced suffix (+fused yacc zero) + d-major sparse + finalize
    chunk_sum_kernel<<<dim3(DIN / 256, NCHK), blk>>>(delta, Sbuf);
    suffix_write_kernel<<<dim3(DIN / 256, NCHK), blk>>>(delta, Sbuf, Rbuf, yacc);
    scan_sparse_kernel<<<(DIN * NST) / 256, blk>>>(delta, xi, xdbl, A_log, Rbuf, yacc);
    finalize_y_kernel<<<(LSEQ * DIN / 4 + 255) / 256, blk>>>(yacc, xi, xr, Dv, y);

    // 6) out = y @ W_out + b_out  — plain TF32 cp.async
    gemm_tf32_async_kernel<1><<<dim3(DM / 128, LSEQ / 128), blk, SMEMA>>>(
        y, wout, b_out, out, LSEQ, DM, DIN, DIN, DM, DM);
}